// round 10
// baseline (speedup 1.0000x reference)
#include <cuda_runtime.h>
#include <cuda_fp16.h>
#include <cstdint>

// Problem dims
#define B_  2
#define C_  4
#define D_  64
#define H_  160
#define W_  160
#define HW_ (H_ * W_)            // 25600
#define BC_ (B_ * C_)            // 8
#define NSLICE (BC_ * D_)        // 512
#define NVOX_PER_CH (B_ * D_ * H_ * W_)  // 3,276,800

// Gaussian window (k=11, sigma=1.5), normalized, symmetric.
#define GW0 0.00102838f
#define GW1 0.00759876f
#define GW2 0.03600077f
#define GW3 0.10936069f
#define GW4 0.21300554f
#define GW5 0.26601173f

#define SSIM_C1 1.0e-4f
#define SSIM_C2 9.0e-4f

__host__ __device__ constexpr float gw(int t) {
    return t == 0 ? GW0 : t == 1 ? GW1 : t == 2 ? GW2 : t == 3 ? GW3 :
           t == 4 ? GW4 : t == 5 ? GW5 : t == 6 ? GW4 : t == 7 ? GW3 :
           t == 8 ? GW2 : t == 9 ? GW1 : GW0;
}

// ---------------------------------------------------------------------------
// Packed fp32x2 ops (Blackwell FFMA2/FMUL2; full fp32 precision per lane).
// float2 <-> b64 bitcasts are register-pair reinterprets (free).
// ---------------------------------------------------------------------------
__device__ __forceinline__ float2 ffma2(float2 a, float2 b, float2 c) {
    unsigned long long ua = *reinterpret_cast<unsigned long long*>(&a);
    unsigned long long ub = *reinterpret_cast<unsigned long long*>(&b);
    unsigned long long uc = *reinterpret_cast<unsigned long long*>(&c);
    unsigned long long ud;
    asm("fma.rn.f32x2 %0, %1, %2, %3;" : "=l"(ud) : "l"(ua), "l"(ub), "l"(uc));
    return *reinterpret_cast<float2*>(&ud);
}
__device__ __forceinline__ float2 fmul2(float2 a, float2 b) {
    unsigned long long ua = *reinterpret_cast<unsigned long long*>(&a);
    unsigned long long ub = *reinterpret_cast<unsigned long long*>(&b);
    unsigned long long ud;
    asm("mul.rn.f32x2 %0, %1, %2;" : "=l"(ud) : "l"(ua), "l"(ub));
    return *reinterpret_cast<float2*>(&ud);
}
__device__ __forceinline__ float2 bcast2(float w) { return make_float2(w, w); }

// fp16 scratch: (mu1,mu2), (E11,E22) as half2, E12 as half. 131 MB total.
// Storage-only fp16 (R8-proven); all arithmetic is fp32.
__device__ __half2 gA[(long long)NSLICE * HW_];   // (mu1, mu2)
__device__ __half2 gB[(long long)NSLICE * HW_];   // (E11, E22)
__device__ __half  gC[(long long)NSLICE * HW_];   // E12
__device__ float   g_acc[C_];

struct alignas(16) F2x2 { float2 h[2]; };

// Packed 11-tap conv over v[S..S+10] of a float2 register array.
template <int S, int N>
__device__ __forceinline__ float2 convp(const float2 (&v)[N]) {
    float2 s = fmul2(v[S], bcast2(GW0));
#pragma unroll
    for (int k = 1; k < 11; k++) s = ffma2(v[S + k], bcast2(gw(k)), s);
    return s;
}

// Scalar fp32 11-tap conv.
template <int J, int N>
__device__ __forceinline__ float convs(const float (&v)[N]) {
    float s = v[J] * GW0;
#pragma unroll
    for (int k = 1; k < 11; k++) s = fmaf(v[J + k], gw(k), s);
    return s;
}

// ---------------------------------------------------------------------------
// Pass A: 32x32 tile per D-slice; separable W-then-H conv with f32x2 pairs.
// smem: float2 input tile (x1,x2) + float2/scalar mids -> 47 KB, 3 CTAs/SM.
// ---------------------------------------------------------------------------
#define TS 32
#define HALO 5
#define TIN 42   // TS + 2*HALO rows
#define SNX 48   // input cols (j <-> gx = tx0 - 8 + j)
#define MNX 36   // mid row entries (float2)
#define MCX 40   // midC row entries (float)

__global__ void __launch_bounds__(256) passA_kernel(
    const float* __restrict__ img1, const float* __restrict__ img2) {
    __shared__ float2 sp[TIN][SNX];         // (x1,x2), 16.1 KB
    __shared__ float2 midA[TIN][MNX];       // (mu1,mu2)-partial, 12.1 KB
    __shared__ float2 midB[TIN][MNX];       // (E11,E22)-partial, 12.1 KB
    __shared__ float  midC[TIN][MCX];       // E12-partial, 6.7 KB

    const int slice = blockIdx.z;             // bc*D + d
    const int ty0 = blockIdx.y * TS;
    const int tx0 = blockIdx.x * TS;
    const int tid = threadIdx.x;

    const float4* p1 = (const float4*)(img1 + (long long)slice * HW_);
    const float4* p2 = (const float4*)(img2 + (long long)slice * HW_);

    // Phase 1: vector halo load, interleave to (x1,x2) pairs. 42x12 items.
    for (int i = tid; i < TIN * 12; i += 256) {
        int y = i / 12, k = i - y * 12;
        int gy = ty0 + y - HALO;
        int gx0 = tx0 - 8 + 4 * k;
        float4 a = make_float4(0.f, 0.f, 0.f, 0.f);
        float4 b = a;
        if (((unsigned)gy < (unsigned)H_) && ((unsigned)gx0 < (unsigned)W_)) {
            int gi = (gy * W_ + gx0) >> 2;
            a = p1[gi];
            b = p2[gi];
        }
        F2x2 t0, t1;
        t0.h[0] = make_float2(a.x, b.x);
        t0.h[1] = make_float2(a.y, b.y);
        t1.h[0] = make_float2(a.z, b.z);
        t1.h[1] = make_float2(a.w, b.w);
        *(F2x2*)&sp[y][4 * k] = t0;
        *(F2x2*)&sp[y][4 * k + 2] = t1;
    }
    __syncthreads();

    // Phase 2: W-conv. 42 rows x 8 x-quads = 336 items.
    // Output x0+o uses taps p[o+3 .. o+13].
    for (int i = tid; i < TIN * 8; i += 256) {
        int y = i >> 3;
        int x0 = (i & 7) << 2;
        float2 p[20];
#pragma unroll
        for (int k = 0; k < 10; k++)
            *(F2x2*)&p[2 * k] = *(const F2x2*)&sp[y][x0 + 2 * k];

        // mu-pair chain
        {
            F2x2 r0, r1;
            r0.h[0] = convp<3>(p);  r0.h[1] = convp<4>(p);
            r1.h[0] = convp<5>(p);  r1.h[1] = convp<6>(p);
            *(F2x2*)&midA[y][x0] = r0;
            *(F2x2*)&midA[y][x0 + 2] = r1;
        }
        // E-pair chain over (x1^2, x2^2)
        {
            float2 sq[14];
#pragma unroll
            for (int t = 0; t < 14; t++) sq[t] = fmul2(p[t + 3], p[t + 3]);
            F2x2 r0, r1;
            r0.h[0] = convp<0>(sq); r0.h[1] = convp<1>(sq);
            r1.h[0] = convp<2>(sq); r1.h[1] = convp<3>(sq);
            *(F2x2*)&midB[y][x0] = r0;
            *(F2x2*)&midB[y][x0 + 2] = r1;
        }
        // e12 scalar chain over x1*x2
        {
            float cr[14];
#pragma unroll
            for (int t = 0; t < 14; t++) cr[t] = p[t + 3].x * p[t + 3].y;
            float4 r;
            r.x = convs<0>(cr); r.y = convs<1>(cr);
            r.z = convs<2>(cr); r.w = convs<3>(cr);
            *(float4*)&midC[y][x0] = r;
        }
    }
    __syncthreads();

    // Phase 3: H-conv. Thread -> (x = tid&31, y0 = (tid>>5)*4).
    {
        int x = tid & 31;
        int y0 = (tid >> 5) << 2;
        long long vox = (long long)slice * HW_ + (long long)(ty0 + y0) * W_ + (tx0 + x);

        float2 v[14];
#pragma unroll
        for (int t = 0; t < 14; t++) v[t] = midA[y0 + t][x];
        {
            float2 r0 = convp<0>(v), r1 = convp<1>(v);
            float2 r2 = convp<2>(v), r3 = convp<3>(v);
            gA[vox + 0 * W_] = __floats2half2_rn(r0.x, r0.y);
            gA[vox + 1 * W_] = __floats2half2_rn(r1.x, r1.y);
            gA[vox + 2 * W_] = __floats2half2_rn(r2.x, r2.y);
            gA[vox + 3 * W_] = __floats2half2_rn(r3.x, r3.y);
        }
#pragma unroll
        for (int t = 0; t < 14; t++) v[t] = midB[y0 + t][x];
        {
            float2 r0 = convp<0>(v), r1 = convp<1>(v);
            float2 r2 = convp<2>(v), r3 = convp<3>(v);
            gB[vox + 0 * W_] = __floats2half2_rn(r0.x, r0.y);
            gB[vox + 1 * W_] = __floats2half2_rn(r1.x, r1.y);
            gB[vox + 2 * W_] = __floats2half2_rn(r2.x, r2.y);
            gB[vox + 3 * W_] = __floats2half2_rn(r3.x, r3.y);
        }
        {
            float f[14];
#pragma unroll
            for (int t = 0; t < 14; t++) f[t] = midC[y0 + t][x];
            gC[vox + 0 * W_] = __float2half_rn(convs<0>(f));
            gC[vox + 1 * W_] = __float2half_rn(convs<1>(f));
            gC[vox + 2 * W_] = __float2half_rn(convs<2>(f));
            gC[vox + 3 * W_] = __float2half_rn(convs<3>(f));
        }
    }
}

// ---------------------------------------------------------------------------
// Pass B: D-conv via 13-deep rotating rings (slot = plane % 13).
// mu-ring and E-ring as float2 (FFMA2 chains); e12-ring scalar fp32.
// Refill at step d loads plane d+8 (fp16 -> fp32), first consumed at d+3.
// ---------------------------------------------------------------------------
template <int J>
__device__ __forceinline__ float2 convr2(const float2 (&r)[13]) {
    float2 s = fmul2(r[(J + 8) % 13], bcast2(GW0));
#pragma unroll
    for (int k = 1; k < 11; k++)
        s = ffma2(r[(J + 8 + k) % 13], bcast2(gw(k)), s);
    return s;
}

template <int J>
__device__ __forceinline__ float convr1(const float (&r)[13]) {
    float s = r[(J + 8) % 13] * GW0;
#pragma unroll
    for (int k = 1; k < 11; k++) s = fmaf(r[(J + 8 + k) % 13], gw(k), s);
    return s;
}

template <int J, bool LOAD>
__device__ __forceinline__ void stepJ(
    float2 (&rA)[13], float2 (&rB)[13], float (&rC)[13],
    const __half2* __restrict__ tA, const __half2* __restrict__ tB,
    const __half* __restrict__ tC,
    int o, float& acc) {
    float2 mu = convr2<J>(rA);
    float2 ee = convr2<J>(rB);
    float e12 = convr1<J>(rC);

    float mu1sq = mu.x * mu.x;
    float mu2sq = mu.y * mu.y;
    float mu12 = mu.x * mu.y;
    float s11 = ee.x - mu1sq;
    float s22 = ee.y - mu2sq;
    float s12 = e12 - mu12;

    float num = (2.f * mu12 + SSIM_C1) * (2.f * s12 + SSIM_C2);
    float den = (mu1sq + mu2sq + SSIM_C1) * (s11 + s22 + SSIM_C2);
    acc += __fdividef(num, den);

    constexpr int RS = (J + 8) % 13;
    if (LOAD) {
        rA[RS] = __half22float2(tA[o]);
        rB[RS] = __half22float2(tB[o]);
        rC[RS] = __half2float(tC[o]);
    } else {
        rA[RS] = make_float2(0.f, 0.f);
        rB[RS] = make_float2(0.f, 0.f);
        rC[RS] = 0.f;
    }
}

__global__ void __launch_bounds__(160) passB_kernel() {
    const int bid = blockIdx.x;          // (b*C + c)*H + y
    const int y = bid % H_;
    const int bc = bid / H_;             // b*C + c
    const int c = bc % C_;
    const int x = threadIdx.x;           // 0..159

    const int colbase = bc * D_ * HW_ + y * W_ + x;
    const __half2* tA = gA + colbase;
    const __half2* tB = gB + colbase;
    const __half*  tC = gC + colbase;

    float2 rA[13], rB[13];
    float rC[13];
#pragma unroll
    for (int k = 0; k < 8; k++) {
        int o = k * HW_;
        rA[k] = __half22float2(tA[o]);
        rB[k] = __half22float2(tB[o]);
        rC[k] = __half2float(tC[o]);
    }
#pragma unroll
    for (int k = 8; k < 13; k++) {
        rA[k] = make_float2(0.f, 0.f);
        rB[k] = make_float2(0.f, 0.f);
        rC[k] = 0.f;
    }

    float acc = 0.f;
    int o = 8 * HW_;  // step d refills plane d+8

#define STEP(J, L) stepJ<J, L>(rA, rB, rC, tA, tB, tC, o, acc); o += HW_;

    // d = 0..51 : four full rotations of 13 (refills planes 8..59)
#pragma unroll 1
    for (int r = 0; r < 4; r++) {
        STEP(0, true)  STEP(1, true)  STEP(2, true)  STEP(3, true)
        STEP(4, true)  STEP(5, true)  STEP(6, true)  STEP(7, true)
        STEP(8, true)  STEP(9, true)  STEP(10, true) STEP(11, true)
        STEP(12, true)
    }
    // d = 52..63 : refill valid while d+8 <= 63
    STEP(0, true)  STEP(1, true)  STEP(2, true)  STEP(3, true)
    STEP(4, false) STEP(5, false) STEP(6, false) STEP(7, false)
    STEP(8, false) STEP(9, false) STEP(10, false) STEP(11, false)
#undef STEP

    __shared__ float red[5];
#pragma unroll
    for (int off = 16; off > 0; off >>= 1)
        acc += __shfl_down_sync(0xffffffffu, acc, off);
    if ((threadIdx.x & 31) == 0) red[threadIdx.x >> 5] = acc;
    __syncthreads();
    if (threadIdx.x == 0) {
        float s = red[0] + red[1] + red[2] + red[3] + red[4];
        atomicAdd(&g_acc[c], s);
    }
}

// Reads per-channel sums, writes loss, re-zeroes g_acc for the next replay.
// First call relies on .bss zero-init.
__global__ void final_kernel(float* __restrict__ out) {
    int c = threadIdx.x;
    if (c < C_) {
        out[c] = 1.f - g_acc[c] * (1.f / (float)NVOX_PER_CH);
        g_acc[c] = 0.f;
    }
}

extern "C" void kernel_launch(void* const* d_in, const int* in_sizes, int n_in,
                              void* d_out, int out_size) {
    (void)in_sizes; (void)n_in; (void)out_size;
    const float* img1 = (const float*)d_in[0];
    const float* img2 = (const float*)d_in[1];
    float* out = (float*)d_out;

    dim3 gA_(W_ / TS, H_ / TS, NSLICE);  // (5, 5, 512)
    passA_kernel<<<gA_, 256>>>(img1, img2);
    passB_kernel<<<BC_ * H_, 160>>>();
    final_kernel<<<1, 32>>>(out);
}

// round 12
// speedup vs baseline: 1.5691x; 1.5691x over previous
#include <cuda_runtime.h>
#include <cuda_fp16.h>
#include <cstdint>

// Problem dims
#define B_  2
#define C_  4
#define D_  64
#define H_  160
#define W_  160
#define HW_ (H_ * W_)            // 25600
#define BC_ (B_ * C_)            // 8
#define NSLICE (BC_ * D_)        // 512
#define NVOX_PER_CH (B_ * D_ * H_ * W_)  // 3,276,800

// Gaussian window (k=11, sigma=1.5), normalized, symmetric.
#define GW0 0.00102838f
#define GW1 0.00759876f
#define GW2 0.03600077f
#define GW3 0.10936069f
#define GW4 0.21300554f
#define GW5 0.26601173f

#define SSIM_C1 1.0e-4f
#define SSIM_C2 9.0e-4f

__host__ __device__ constexpr float gw(int t) {
    return t == 0 ? GW0 : t == 1 ? GW1 : t == 2 ? GW2 : t == 3 ? GW3 :
           t == 4 ? GW4 : t == 5 ? GW5 : t == 6 ? GW4 : t == 7 ? GW3 :
           t == 8 ? GW2 : t == 9 ? GW1 : GW0;
}

// fp16 scratch: (mu1,mu2), (E11,E22) as half2, E12 as half. 131 MB total.
// Storage-only fp16 (R8-proven); all arithmetic fp32.
__device__ __half2 gA[(long long)NSLICE * HW_];   // (mu1, mu2)
__device__ __half2 gB[(long long)NSLICE * HW_];   // (E11, E22)
__device__ __half  gC[(long long)NSLICE * HW_];   // E12
__device__ float   g_acc[C_];

// fp32 11-tap conv over v[J..J+10] of an N-float register array.
template <int J, int N>
__device__ __forceinline__ float convs(const float (&v)[N]) {
    float s = v[J] * GW0;
#pragma unroll
    for (int k = 1; k < 11; k++) s = fmaf(v[J + k], gw(k), s);
    return s;
}

// ---------------------------------------------------------------------------
// Pass A: 32x32 tile per D-slice; separable W-then-H conv, fp32 math.
// Input tile: half2(x1,x2)-packed (halves phase-2 smem read bytes).
// Mids: fp32. Phase 3: 8-y sliding windows, field-split across warp halves.
// ---------------------------------------------------------------------------
#define TS 32
#define HALO 5
#define TIN 42   // TS + 2*HALO rows
#define SNX 48   // input cols (j <-> gx = tx0 - 8 + j)
#define MNX 36   // mid row pad (16B-aligned)

__global__ void __launch_bounds__(256) passA_kernel(
    const float* __restrict__ img1, const float* __restrict__ img2) {
    __shared__ __half2 sp[TIN][SNX];     // (x1,x2) per pixel, 8.06 KB
    __shared__ float mid[5][TIN][MNX];   // fp32 mids, 30.2 KB  (total 38.3 KB)

    const int slice = blockIdx.z;             // bc*D + d
    const int ty0 = blockIdx.y * TS;
    const int tx0 = blockIdx.x * TS;
    const int tid = threadIdx.x;

    const float4* p1 = (const float4*)(img1 + (long long)slice * HW_);
    const float4* p2 = (const float4*)(img2 + (long long)slice * HW_);

    // Phase 1: vector halo load + pack to half2. 42x12 items, one STS.128 each.
    for (int i = tid; i < TIN * 12; i += 256) {
        int y = i / 12, k = i - y * 12;
        int gy = ty0 + y - HALO;
        int gx0 = tx0 - 8 + 4 * k;
        float4 a = make_float4(0.f, 0.f, 0.f, 0.f);
        float4 b = a;
        if (((unsigned)gy < (unsigned)H_) && ((unsigned)gx0 < (unsigned)W_)) {
            int gi = (gy * W_ + gx0) >> 2;
            a = p1[gi];
            b = p2[gi];
        }
        union { __half2 h[4]; uint4 u; } t;
        t.h[0] = __floats2half2_rn(a.x, b.x);
        t.h[1] = __floats2half2_rn(a.y, b.y);
        t.h[2] = __floats2half2_rn(a.z, b.z);
        t.h[3] = __floats2half2_rn(a.w, b.w);
        *(uint4*)&sp[y][4 * k] = t.u;
    }
    __syncthreads();

    // Phase 2: W-conv. 42 rows x 8 x-quads = 336 items.
    // Outputs x0..x0+3 need entries x0+3..x0+16; load x0..x0+19 = 5 LDS.128.
    for (int i = tid; i < TIN * 8; i += 256) {
        int y = i >> 3;
        int x0 = (i & 7) << 2;
        __half2 w[20];
#pragma unroll
        for (int k = 0; k < 5; k++)
            *(uint4*)&w[4 * k] = *(const uint4*)&sp[y][x0 + 4 * k];
        float A[14], Bv[14];
#pragma unroll
        for (int t = 0; t < 14; t++) {
            float2 f = __half22float2(w[t + 3]);
            A[t] = f.x;
            Bv[t] = f.y;
        }
        float4 r;
        r.x = convs<0>(A); r.y = convs<1>(A); r.z = convs<2>(A); r.w = convs<3>(A);
        *(float4*)&mid[0][y][x0] = r;
        r.x = convs<0>(Bv); r.y = convs<1>(Bv); r.z = convs<2>(Bv); r.w = convs<3>(Bv);
        *(float4*)&mid[1][y][x0] = r;
        {
            float sq[14];
#pragma unroll
            for (int t = 0; t < 14; t++) sq[t] = A[t] * A[t];
            r.x = convs<0>(sq); r.y = convs<1>(sq); r.z = convs<2>(sq); r.w = convs<3>(sq);
            *(float4*)&mid[2][y][x0] = r;
        }
        {
            float sq[14];
#pragma unroll
            for (int t = 0; t < 14; t++) sq[t] = Bv[t] * Bv[t];
            r.x = convs<0>(sq); r.y = convs<1>(sq); r.z = convs<2>(sq); r.w = convs<3>(sq);
            *(float4*)&mid[3][y][x0] = r;
        }
        {
            float sq[14];
#pragma unroll
            for (int t = 0; t < 14; t++) sq[t] = A[t] * Bv[t];
            r.x = convs<0>(sq); r.y = convs<1>(sq); r.z = convs<2>(sq); r.w = convs<3>(sq);
            *(float4*)&mid[4][y][x0] = r;
        }
    }
    __syncthreads();

    // Phase 3: H-conv, 8-y sliding windows (18-row reads per field).
    // Warps 0-3: fields 0,1 -> gA. Warps 4-7: fields 2,3 -> gB and 4 -> gC.
    {
        int t128 = tid & 127;
        int x = t128 & 31;
        int y0 = (t128 >> 5) << 3;   // 0, 8, 16, 24
        int half = tid >> 7;         // 0 or 1
        long long vox = (long long)slice * HW_ + (long long)(ty0 + y0) * W_ + (tx0 + x);
        float v[18];
#define HCONV8(DST)                                                    \
        DST[0] = convs<0>(v); DST[1] = convs<1>(v);                    \
        DST[2] = convs<2>(v); DST[3] = convs<3>(v);                    \
        DST[4] = convs<4>(v); DST[5] = convs<5>(v);                    \
        DST[6] = convs<6>(v); DST[7] = convs<7>(v);
        if (half == 0) {
            float m1[8], m2[8];
#pragma unroll
            for (int t = 0; t < 18; t++) v[t] = mid[0][y0 + t][x];
            HCONV8(m1)
#pragma unroll
            for (int t = 0; t < 18; t++) v[t] = mid[1][y0 + t][x];
            HCONV8(m2)
#pragma unroll
            for (int u = 0; u < 8; u++)
                gA[vox + u * W_] = __floats2half2_rn(m1[u], m2[u]);
        } else {
            float e1[8], e2[8];
#pragma unroll
            for (int t = 0; t < 18; t++) v[t] = mid[2][y0 + t][x];
            HCONV8(e1)
#pragma unroll
            for (int t = 0; t < 18; t++) v[t] = mid[3][y0 + t][x];
            HCONV8(e2)
#pragma unroll
            for (int u = 0; u < 8; u++)
                gB[vox + u * W_] = __floats2half2_rn(e1[u], e2[u]);
#pragma unroll
            for (int t = 0; t < 18; t++) v[t] = mid[4][y0 + t][x];
            HCONV8(e1)
#pragma unroll
            for (int u = 0; u < 8; u++)
                gC[vox + u * W_] = __float2half_rn(e1[u]);
        }
#undef HCONV8
    }
}

// ---------------------------------------------------------------------------
// Pass B (exact R8): D-conv via 13-deep rotating register ring
// (slot = plane % 13), fp32 rings, fp16 loads. Refill at step d loads
// plane d+8, first consumed at step d+3.
// ---------------------------------------------------------------------------
template <int J>
__device__ __forceinline__ float conv13(const float (&r)[13]) {
    float s = r[(J + 8) % 13] * GW0;
#pragma unroll
    for (int k = 1; k < 11; k++) s = fmaf(r[(J + 8 + k) % 13], gw(k), s);
    return s;
}

template <int J, bool LOAD>
__device__ __forceinline__ void stepJ(
    float (&a)[13], float (&b)[13], float (&c11)[13],
    float (&c22)[13], float (&c12)[13],
    const __half2* __restrict__ tA, const __half2* __restrict__ tB,
    const __half* __restrict__ tC,
    int o, float& acc) {
    float mu1 = conv13<J>(a);
    float mu2 = conv13<J>(b);
    float e11 = conv13<J>(c11);
    float e22 = conv13<J>(c22);
    float e12 = conv13<J>(c12);

    float mu1sq = mu1 * mu1;
    float mu2sq = mu2 * mu2;
    float mu12 = mu1 * mu2;
    float s11 = e11 - mu1sq;
    float s22 = e22 - mu2sq;
    float s12 = e12 - mu12;

    float num = (2.f * mu12 + SSIM_C1) * (2.f * s12 + SSIM_C2);
    float den = (mu1sq + mu2sq + SSIM_C1) * (s11 + s22 + SSIM_C2);
    acc += __fdividef(num, den);

    constexpr int RS = (J + 8) % 13;
    if (LOAD) {
        float2 ab = __half22float2(tA[o]);
        float2 ee = __half22float2(tB[o]);
        a[RS] = ab.x; b[RS] = ab.y;
        c11[RS] = ee.x; c22[RS] = ee.y;
        c12[RS] = __half2float(tC[o]);
    } else {
        a[RS] = 0.f; b[RS] = 0.f; c11[RS] = 0.f; c22[RS] = 0.f; c12[RS] = 0.f;
    }
}

__global__ void __launch_bounds__(160) passB_kernel() {
    const int bid = blockIdx.x;          // (b*C + c)*H + y
    const int y = bid % H_;
    const int bc = bid / H_;             // b*C + c
    const int c = bc % C_;
    const int x = threadIdx.x;           // 0..159

    const int colbase = bc * D_ * HW_ + y * W_ + x;
    const __half2* tA = gA + colbase;
    const __half2* tB = gB + colbase;
    const __half*  tC = gC + colbase;

    float a[13], b[13], c11[13], c22[13], c12[13];
#pragma unroll
    for (int k = 0; k < 8; k++) {
        int o = k * HW_;
        float2 ab = __half22float2(tA[o]);
        float2 ee = __half22float2(tB[o]);
        a[k] = ab.x; b[k] = ab.y;
        c11[k] = ee.x; c22[k] = ee.y;
        c12[k] = __half2float(tC[o]);
    }
#pragma unroll
    for (int k = 8; k < 13; k++) {
        a[k] = 0.f; b[k] = 0.f; c11[k] = 0.f; c22[k] = 0.f; c12[k] = 0.f;
    }

    float acc = 0.f;
    int o = 8 * HW_;  // step d refills plane d+8

#define STEP(J, L) stepJ<J, L>(a, b, c11, c22, c12, tA, tB, tC, o, acc); o += HW_;

    // d = 0..51 : four full rotations of 13 (refills planes 8..59)
#pragma unroll 1
    for (int r = 0; r < 4; r++) {
        STEP(0, true)  STEP(1, true)  STEP(2, true)  STEP(3, true)
        STEP(4, true)  STEP(5, true)  STEP(6, true)  STEP(7, true)
        STEP(8, true)  STEP(9, true)  STEP(10, true) STEP(11, true)
        STEP(12, true)
    }
    // d = 52..63 : refill valid while d+8 <= 63
    STEP(0, true)  STEP(1, true)  STEP(2, true)  STEP(3, true)
    STEP(4, false) STEP(5, false) STEP(6, false) STEP(7, false)
    STEP(8, false) STEP(9, false) STEP(10, false) STEP(11, false)
#undef STEP

    __shared__ float red[5];
#pragma unroll
    for (int off = 16; off > 0; off >>= 1)
        acc += __shfl_down_sync(0xffffffffu, acc, off);
    if ((threadIdx.x & 31) == 0) red[threadIdx.x >> 5] = acc;
    __syncthreads();
    if (threadIdx.x == 0) {
        float s = red[0] + red[1] + red[2] + red[3] + red[4];
        atomicAdd(&g_acc[c], s);
    }
}

// Reads per-channel sums, writes loss, re-zeroes g_acc for the next replay.
// First call relies on .bss zero-init.
__global__ void final_kernel(float* __restrict__ out) {
    int c = threadIdx.x;
    if (c < C_) {
        out[c] = 1.f - g_acc[c] * (1.f / (float)NVOX_PER_CH);
        g_acc[c] = 0.f;
    }
}

extern "C" void kernel_launch(void* const* d_in, const int* in_sizes, int n_in,
                              void* d_out, int out_size) {
    (void)in_sizes; (void)n_in; (void)out_size;
    const float* img1 = (const float*)d_in[0];
    const float* img2 = (const float*)d_in[1];
    float* out = (float*)d_out;

    dim3 gA_(W_ / TS, H_ / TS, NSLICE);  // (5, 5, 512)
    passA_kernel<<<gA_, 256>>>(img1, img2);
    passB_kernel<<<BC_ * H_, 160>>>();
    final_kernel<<<1, 32>>>(out);
}